// round 15
// baseline (speedup 1.0000x reference)
#include <cuda_runtime.h>
#include <math.h>
#include <stdint.h>

#define Nn   16
#define Pp   866
#define CIN  1280
#define Cc   512
#define HWs  64
#define NOUT 10
#define PW   5130          // (Cc+1)*NOUT
#define BN_EPS 0.001f

typedef unsigned long long ull;
typedef unsigned int uint32;

__device__ __align__(16) float g_f[Nn * Cc * HWs];

// ---------- helpers ----------
__device__ __forceinline__ void cp16(void* dst, const void* src) {
    uint32 d = (uint32)__cvta_generic_to_shared(dst);
    asm volatile("cp.async.cg.shared.global [%0], [%1], 16;" :: "r"(d), "l"(src));
}
#define CP_COMMIT() asm volatile("cp.async.commit_group;")
#define CP_WAIT0()  asm volatile("cp.async.wait_group 0;")
#define CP_WAIT1()  asm volatile("cp.async.wait_group 1;")

__device__ __forceinline__ void mma_tf32(float* d, uint32 a0, uint32 a1,
                                         uint32 a2, uint32 a3,
                                         uint32 b0, uint32 b1) {
    asm volatile(
        "mma.sync.aligned.m16n8k8.row.col.f32.tf32.tf32.f32 "
        "{%0,%1,%2,%3}, {%4,%5,%6,%7}, {%8,%9}, {%0,%1,%2,%3};"
        : "+f"(d[0]), "+f"(d[1]), "+f"(d[2]), "+f"(d[3])
        : "r"(a0), "r"(a1), "r"(a2), "r"(a3), "r"(b0), "r"(b1));
}
__device__ __forceinline__ uint32 fbits(float x) {
    uint32 r; asm("mov.b32 %0, %1;" : "=r"(r) : "f"(x)); return r;
}

__device__ __forceinline__ float wmax(float v) {
    #pragma unroll
    for (int o = 16; o > 0; o >>= 1)
        v = fmaxf(v, __shfl_xor_sync(0xffffffffu, v, o));
    return v;
}
__device__ __forceinline__ float wsum(float v) {
    #pragma unroll
    for (int o = 16; o > 0; o >>= 1)
        v += __shfl_xor_sync(0xffffffffu, v, o);
    return v;
}

// =====================================================================
// Kernel 1: conv 1x1 + BN + SiLU via tf32 mma.sync  (R13 winner)
// =====================================================================
#define CNCH  40
#define CW_F  2304
#define CB_F  2304
#define CSTG  (CW_F + CB_F)

__global__ void __launch_bounds__(256)
conv_kernel(const float* __restrict__ feat,
            const float* __restrict__ convw,
            const float* __restrict__ gamma,
            const float* __restrict__ beta,
            const float* __restrict__ mean,
            const float* __restrict__ var)
{
    const int n  = blockIdx.y;
    const int cb = blockIdx.x * 64;
    const int t  = threadIdx.x;
    const int warp = t >> 5;
    const int lane = t & 31;
    const int r4 = lane >> 2;
    const int c4 = lane & 3;
    const int tile  = warp & 3;
    const int khalf = warp >> 2;

    __shared__ __align__(16) float smem[2 * CSTG];

    const float* fsrc = feat + (size_t)n * CIN * HWs;
    const float* wsrc = convw + (size_t)cb * CIN;

    const int sc = t >> 2;
    const int sq = t & 3;

    {
        float* W0 = smem;
        float* B0 = smem + CW_F;
        #pragma unroll
        for (int i = 0; i < 2; i++)
            cp16(W0 + sc * 36 + sq * 8 + 4 * i, wsrc + (size_t)sc * CIN + sq * 8 + 4 * i);
        #pragma unroll
        for (int i = 0; i < 2; i++) {
            int idx = t + 256 * i;
            int k = idx >> 4, off = idx & 15;
            cp16(B0 + k * 72 + off * 4, fsrc + k * 64 + off * 4);
        }
        CP_COMMIT();
    }

    float d[8][4];
    #pragma unroll
    for (int tt = 0; tt < 8; tt++)
        #pragma unroll
        for (int q = 0; q < 4; q++) d[tt][q] = 0.0f;

    const int arow_lo = (tile * 16 + r4) * 36;
    const int arow_hi = (tile * 16 + r4 + 8) * 36;
    const int kbase = khalf * 16;

    int buf = 0;
    for (int ch = 0; ch < CNCH; ch++) {
        if (ch + 1 < CNCH) {
            float* Wn = smem + (buf ^ 1) * CSTG;
            float* Bn = Wn + CW_F;
            const float* ws = wsrc + (ch + 1) * 32;
            const float* fs = fsrc + (ch + 1) * 32 * 64;
            #pragma unroll
            for (int i = 0; i < 2; i++)
                cp16(Wn + sc * 36 + sq * 8 + 4 * i, ws + (size_t)sc * CIN + sq * 8 + 4 * i);
            #pragma unroll
            for (int i = 0; i < 2; i++) {
                int idx = t + 256 * i;
                int k = idx >> 4, off = idx & 15;
                cp16(Bn + k * 72 + off * 4, fs + k * 64 + off * 4);
            }
            CP_COMMIT();
            CP_WAIT1();
        } else {
            CP_WAIT0();
        }
        __syncthreads();

        const float* W = smem + buf * CSTG;
        const float* B = W + CW_F;
        #pragma unroll
        for (int s = 0; s < 2; s++) {
            const int kl = kbase + s * 8;
            uint32 a0 = fbits(W[arow_lo + kl + c4]);
            uint32 a1 = fbits(W[arow_hi + kl + c4]);
            uint32 a2 = fbits(W[arow_lo + kl + c4 + 4]);
            uint32 a3 = fbits(W[arow_hi + kl + c4 + 4]);
            const float* Bs = B + (kl + c4) * 72 + r4;
            #pragma unroll
            for (int tt = 0; tt < 8; tt++) {
                uint32 b0 = fbits(Bs[tt * 8]);
                uint32 b1 = fbits(Bs[tt * 8 + 288]);
                mma_tf32(d[tt], a0, a1, a2, a3, b0, b1);
            }
        }
        __syncthreads();
        buf ^= 1;
    }

    float* comb = smem;
    if (khalf == 1) {
        float* cb_ = comb + tile * 1088;
        #pragma unroll
        for (int tt = 0; tt < 8; tt++) {
            int col = tt * 8 + c4 * 2;
            *(float2*)(cb_ + r4 * 68 + col)       = make_float2(d[tt][0], d[tt][1]);
            *(float2*)(cb_ + (r4 + 8) * 68 + col) = make_float2(d[tt][2], d[tt][3]);
        }
    }
    __syncthreads();

    if (khalf == 0) {
        const float* cb_ = comb + tile * 1088;
        #pragma unroll
        for (int tt = 0; tt < 8; tt++) {
            int col = tt * 8 + c4 * 2;
            float2 v0 = *(const float2*)(cb_ + r4 * 68 + col);
            float2 v1 = *(const float2*)(cb_ + (r4 + 8) * 68 + col);
            d[tt][0] += v0.x; d[tt][1] += v0.y;
            d[tt][2] += v1.x; d[tt][3] += v1.y;
        }

        const int c_lo = cb + tile * 16 + r4;
        const int c_hi = c_lo + 8;
        float sc0 = __ldg(gamma + c_lo) * rsqrtf(__ldg(var + c_lo) + BN_EPS);
        float bi0 = __ldg(beta + c_lo) - __ldg(mean + c_lo) * sc0;
        float sc1 = __ldg(gamma + c_hi) * rsqrtf(__ldg(var + c_hi) + BN_EPS);
        float bi1 = __ldg(beta + c_hi) - __ldg(mean + c_hi) * sc1;

        float* o_lo = g_f + ((size_t)n * Cc + c_lo) * HWs;
        float* o_hi = g_f + ((size_t)n * Cc + c_hi) * HWs;
        #pragma unroll
        for (int tt = 0; tt < 8; tt++) {
            int col = tt * 8 + c4 * 2;
            float a0 = d[tt][0] * sc0 + bi0;  a0 = a0 / (1.0f + __expf(-a0));
            float a1 = d[tt][1] * sc0 + bi0;  a1 = a1 / (1.0f + __expf(-a1));
            float a2 = d[tt][2] * sc1 + bi1;  a2 = a2 / (1.0f + __expf(-a2));
            float a3 = d[tt][3] * sc1 + bi1;  a3 = a3 / (1.0f + __expf(-a3));
            *(float2*)(o_lo + col) = make_float2(a0, a1);
            *(float2*)(o_hi + col) = make_float2(a2, a3);
        }
    }
}

// =====================================================================
// Kernel 2: head via tf32 mma.sync, BARRIER-FREE direct-LDG streaming
// grid (55, 16) = 880 blocks, 160 threads = 5 warps, 16 p per block.
// Warp w owns m16 tiles at rows w*16 and w*16+80 (M=160 = 16p x 10j).
// A fragments: LDG straight from weights (L2 dedups block's 16-p span).
// B fragments: LDG from g_f (L2-resident). No smem/barriers in mainloop.
// Epilogue: logits -> smem (stride 68), warp-wide softmax (R12 style).
// =====================================================================
#define PT16  16
#define NPT   55

__global__ void __launch_bounds__(160, 3)
head_mma_kernel(const float* __restrict__ weights, float* __restrict__ out)
{
    const int n    = blockIdx.y;
    const int p0   = blockIdx.x * PT16;
    const int t    = threadIdx.x;
    const int warp = t >> 5;
    const int lane = t & 31;
    const int r4   = lane >> 2;     // 0..7
    const int c4   = lane & 3;      // 0..3

    __shared__ __align__(16) float L[160 * 68];   // 43520 B (epilogue only)

    const float* wn  = weights + (size_t)n * Pp * PW;
    const float* gfn = g_f + (size_t)n * Cc * HWs;

    // ---- per-thread A row pointers (4 rows: tile0 lo/hi, tile1 lo/hi) ----
    const int m0 = warp * 16 + r4;            // tile0 lo row
    int rows[4] = { m0, m0 + 8, m0 + 80, m0 + 88 };
    const float* rp[4];
    #pragma unroll
    for (int i = 0; i < 4; i++) {
        int m = rows[i];
        int pl = m / 10;
        int j  = m - pl * 10;
        int p  = p0 + pl; if (p >= Pp) p = Pp - 1;
        rp[i] = wn + (size_t)p * PW + j + c4 * 10;   // element k = c4
    }

    const float* bb = gfn + c4 * 64 + r4;     // b row k = c4, hw = r4

    float d0[8][4], d1[8][4];
    #pragma unroll
    for (int tt = 0; tt < 8; tt++)
        #pragma unroll
        for (int q = 0; q < 4; q++) { d0[tt][q] = 0.0f; d1[tt][q] = 0.0f; }

    // ---- mainloop: 64 independent k8 steps, no barriers ----
    #pragma unroll 2
    for (int s = 0; s < 64; s++) {
        const int ao = s * 80;                // (s*8)*10 floats
        float a00 = __ldg(rp[0] + ao);
        float a01 = __ldg(rp[1] + ao);
        float a02 = __ldg(rp[0] + ao + 40);
        float a03 = __ldg(rp[1] + ao + 40);
        float a10 = __ldg(rp[2] + ao);
        float a11 = __ldg(rp[3] + ao);
        float a12 = __ldg(rp[2] + ao + 40);
        float a13 = __ldg(rp[3] + ao + 40);

        const float* bs = bb + s * 512;       // k = s*8 + c4
        float b0[8], b1[8];
        #pragma unroll
        for (int tt = 0; tt < 8; tt++) {
            b0[tt] = __ldg(bs + tt * 8);
            b1[tt] = __ldg(bs + 256 + tt * 8);
        }

        uint32 ua00 = fbits(a00), ua01 = fbits(a01), ua02 = fbits(a02), ua03 = fbits(a03);
        uint32 ua10 = fbits(a10), ua11 = fbits(a11), ua12 = fbits(a12), ua13 = fbits(a13);
        #pragma unroll
        for (int tt = 0; tt < 8; tt++) {
            uint32 ub0 = fbits(b0[tt]), ub1 = fbits(b1[tt]);
            mma_tf32(d0[tt], ua00, ua01, ua02, ua03, ub0, ub1);
            mma_tf32(d1[tt], ua10, ua11, ua12, ua13, ub0, ub1);
        }
    }

    // ---- dump logits to smem: L[m][hw], stride 68 ----
    #pragma unroll
    for (int tt = 0; tt < 8; tt++) {
        int col = tt * 8 + c4 * 2;
        *(float2*)(L + rows[0] * 68 + col) = make_float2(d0[tt][0], d0[tt][1]);
        *(float2*)(L + rows[1] * 68 + col) = make_float2(d0[tt][2], d0[tt][3]);
        *(float2*)(L + rows[2] * 68 + col) = make_float2(d1[tt][0], d1[tt][1]);
        *(float2*)(L + rows[3] * 68 + col) = make_float2(d1[tt][2], d1[tt][3]);
    }
    __syncthreads();

    // ---- epilogue: 5 warps x up to 4 p each (pl = warp + rep*5) ----
    {
        const float inv7 = 1.0f / 7.0f;
        const int hw0 = lane * 2;
        const float x0 = (float)(hw0 & 7) * inv7;
        const float x1 = (float)((hw0 + 1) & 7) * inv7;
        const float yv = (float)(hw0 >> 3) * inv7;

        #pragma unroll
        for (int rep = 0; rep < 4; rep++) {
            const int pl = warp + rep * 5;
            if (pl >= PT16) break;
            const int pv = p0 + pl;
            const int p  = (pv < Pp) ? pv : (Pp - 1);

            float bias = 0.0f;
            if (lane < 10)
                bias = __ldg(wn + (size_t)p * PW + Cc * NOUT + lane);

            float l[10][2];
            #pragma unroll
            for (int j = 0; j < 10; j++) {
                float2 v = *(const float2*)(L + (pl * 10 + j) * 68 + hw0);
                float bj = __shfl_sync(0xffffffffu, bias, j);
                l[j][0] = v.x + bj;
                l[j][1] = v.y + bj;
            }

            // xy softmax (channel 1)
            float mx = wmax(fmaxf(l[1][0], l[1][1]));
            float e0 = __expf(l[1][0] - mx);
            float e1 = __expf(l[1][1] - mx);
            float s  = wsum(e0 + e1);
            float sx = wsum(e0 * x0 + e1 * x1);
            float sy = wsum((e0 + e1) * yv);
            float cx = sx / s;
            float cy = sy / s;

            // 2.5D softmax (channels 2..9)
            float m2 = -INFINITY;
            #pragma unroll
            for (int j = 2; j < 10; j++)
                m2 = fmaxf(m2, fmaxf(l[j][0], l[j][1]));
            m2 = wmax(m2);

            float se = 0.0f, sx2 = 0.0f, sy2 = 0.0f, sz = 0.0f, su = 0.0f;
            #pragma unroll
            for (int j = 2; j < 10; j++) {
                float ea = __expf(l[j][0] - m2);
                float eb = __expf(l[j][1] - m2);
                float zs = (float)(j - 2) * inv7;
                se  += ea + eb;
                sx2 += ea * x0 + eb * x1;
                sy2 += (ea + eb) * yv;
                sz  += (ea + eb) * zs;
                su  += ea * l[0][0] + eb * l[0][1];
            }
            se  = wsum(se);
            sx2 = wsum(sx2);
            sy2 = wsum(sy2);
            sz  = wsum(sz);
            su  = wsum(su);

            if (lane == 0 && pv < Pp) {
                float X = sx2 / se, Y = sy2 / se, Z = sz / se, U = su / se;
                float up = fmaxf(U, 0.0f) + log1pf(__expf(-fabsf(U)));
                int gp = n * Pp + pv;
                out[gp * 2 + 0] = X;
                out[gp * 2 + 1] = Y;
                out[Nn * Pp * 2 + gp * 3 + 0] = cx;
                out[Nn * Pp * 2 + gp * 3 + 1] = cy;
                out[Nn * Pp * 2 + gp * 3 + 2] = Z;
                out[Nn * Pp * 5 + gp] = up;
            }
        }
    }
}

// =====================================================================
extern "C" void kernel_launch(void* const* d_in, const int* in_sizes, int n_in,
                              void* d_out, int out_size)
{
    const float* features = (const float*)d_in[0];
    const float* weights  = (const float*)d_in[1];
    const float* conv_w   = (const float*)d_in[2];
    const float* gamma    = (const float*)d_in[3];
    const float* beta     = (const float*)d_in[4];
    const float* mean     = (const float*)d_in[5];
    const float* var      = (const float*)d_in[6];
    float* out = (float*)d_out;

    conv_kernel<<<dim3(8, Nn), 256>>>(features, conv_w, gamma, beta, mean, var);

    head_mma_kernel<<<dim3(NPT, Nn), 160>>>(weights, out);
}

// round 16
// speedup vs baseline: 1.1496x; 1.1496x over previous
#include <cuda_runtime.h>
#include <math.h>
#include <stdint.h>

#define Nn   16
#define Pp   866
#define CIN  1280
#define Cc   512
#define HWs  64
#define NOUT 10
#define PW   5130          // (Cc+1)*NOUT
#define BN_EPS 0.001f

typedef unsigned long long ull;
typedef unsigned int uint32;

__device__ __align__(16) float g_f[Nn * Cc * HWs];
__device__ __align__(16) float g_p0[Nn * Cc * HWs];   // K-split partial 0
__device__ __align__(16) float g_p1[Nn * Cc * HWs];   // K-split partial 1

// ---------- helpers ----------
__device__ __forceinline__ void cp16(void* dst, const void* src) {
    uint32 d = (uint32)__cvta_generic_to_shared(dst);
    asm volatile("cp.async.cg.shared.global [%0], [%1], 16;" :: "r"(d), "l"(src));
}
#define CP_COMMIT() asm volatile("cp.async.commit_group;")
#define CP_WAIT0()  asm volatile("cp.async.wait_group 0;")
#define CP_WAIT1()  asm volatile("cp.async.wait_group 1;")

__device__ __forceinline__ void mma_tf32(float* d, uint32 a0, uint32 a1,
                                         uint32 a2, uint32 a3,
                                         uint32 b0, uint32 b1) {
    asm volatile(
        "mma.sync.aligned.m16n8k8.row.col.f32.tf32.tf32.f32 "
        "{%0,%1,%2,%3}, {%4,%5,%6,%7}, {%8,%9}, {%0,%1,%2,%3};"
        : "+f"(d[0]), "+f"(d[1]), "+f"(d[2]), "+f"(d[3])
        : "r"(a0), "r"(a1), "r"(a2), "r"(a3), "r"(b0), "r"(b1));
}
__device__ __forceinline__ uint32 fbits(float x) {
    uint32 r; asm("mov.b32 %0, %1;" : "=r"(r) : "f"(x)); return r;
}

__device__ __forceinline__ float wmax(float v) {
    #pragma unroll
    for (int o = 16; o > 0; o >>= 1)
        v = fmaxf(v, __shfl_xor_sync(0xffffffffu, v, o));
    return v;
}
__device__ __forceinline__ float wsum(float v) {
    #pragma unroll
    for (int o = 16; o > 0; o >>= 1)
        v += __shfl_xor_sync(0xffffffffu, v, o);
    return v;
}

// =====================================================================
// Kernel 1a: conv partial GEMM via tf32 mma.sync, K split in 2
// grid (8 ctiles, 16 n, 2 kz) = 256 blocks, 256 threads = 8 warps.
// Per block: M=64 c, N=64 hw, K=640 (20 chunks of 32).
// Writes raw fp32 sums to g_p0 / g_p1 (no BN/SiLU).
// =====================================================================
#define CNCH  20                 // chunks per K half
#define CW_F  2304
#define CB_F  2304
#define CSTG  (CW_F + CB_F)

__global__ void __launch_bounds__(256)
conv_part_kernel(const float* __restrict__ feat,
                 const float* __restrict__ convw)
{
    const int n  = blockIdx.y;
    const int cb = blockIdx.x * 64;
    const int kz = blockIdx.z;
    const int t  = threadIdx.x;
    const int warp = t >> 5;
    const int lane = t & 31;
    const int r4 = lane >> 2;
    const int c4 = lane & 3;
    const int tile  = warp & 3;
    const int khalf = warp >> 2;

    __shared__ __align__(16) float smem[2 * CSTG];

    const float* fsrc = feat + (size_t)n * CIN * HWs + (size_t)kz * 640 * HWs;
    const float* wsrc = convw + (size_t)cb * CIN + kz * 640;

    const int sc = t >> 2;
    const int sq = t & 3;

    {
        float* W0 = smem;
        float* B0 = smem + CW_F;
        #pragma unroll
        for (int i = 0; i < 2; i++)
            cp16(W0 + sc * 36 + sq * 8 + 4 * i, wsrc + (size_t)sc * CIN + sq * 8 + 4 * i);
        #pragma unroll
        for (int i = 0; i < 2; i++) {
            int idx = t + 256 * i;
            int k = idx >> 4, off = idx & 15;
            cp16(B0 + k * 72 + off * 4, fsrc + k * 64 + off * 4);
        }
        CP_COMMIT();
    }

    float d[8][4];
    #pragma unroll
    for (int tt = 0; tt < 8; tt++)
        #pragma unroll
        for (int q = 0; q < 4; q++) d[tt][q] = 0.0f;

    const int arow_lo = (tile * 16 + r4) * 36;
    const int arow_hi = (tile * 16 + r4 + 8) * 36;
    const int kbase = khalf * 16;

    int buf = 0;
    for (int ch = 0; ch < CNCH; ch++) {
        if (ch + 1 < CNCH) {
            float* Wn = smem + (buf ^ 1) * CSTG;
            float* Bn = Wn + CW_F;
            const float* ws = wsrc + (ch + 1) * 32;
            const float* fs = fsrc + (ch + 1) * 32 * 64;
            #pragma unroll
            for (int i = 0; i < 2; i++)
                cp16(Wn + sc * 36 + sq * 8 + 4 * i, ws + (size_t)sc * CIN + sq * 8 + 4 * i);
            #pragma unroll
            for (int i = 0; i < 2; i++) {
                int idx = t + 256 * i;
                int k = idx >> 4, off = idx & 15;
                cp16(Bn + k * 72 + off * 4, fs + k * 64 + off * 4);
            }
            CP_COMMIT();
            CP_WAIT1();
        } else {
            CP_WAIT0();
        }
        __syncthreads();

        const float* W = smem + buf * CSTG;
        const float* B = W + CW_F;
        #pragma unroll
        for (int s = 0; s < 2; s++) {
            const int kl = kbase + s * 8;
            uint32 a0 = fbits(W[arow_lo + kl + c4]);
            uint32 a1 = fbits(W[arow_hi + kl + c4]);
            uint32 a2 = fbits(W[arow_lo + kl + c4 + 4]);
            uint32 a3 = fbits(W[arow_hi + kl + c4 + 4]);
            const float* Bs = B + (kl + c4) * 72 + r4;
            #pragma unroll
            for (int tt = 0; tt < 8; tt++) {
                uint32 b0 = fbits(Bs[tt * 8]);
                uint32 b1 = fbits(Bs[tt * 8 + 288]);
                mma_tf32(d[tt], a0, a1, a2, a3, b0, b1);
            }
        }
        __syncthreads();
        buf ^= 1;
    }

    // combine khalf pairs within block via smem, write raw partials
    float* comb = smem;
    if (khalf == 1) {
        float* cb_ = comb + tile * 1088;
        #pragma unroll
        for (int tt = 0; tt < 8; tt++) {
            int col = tt * 8 + c4 * 2;
            *(float2*)(cb_ + r4 * 68 + col)       = make_float2(d[tt][0], d[tt][1]);
            *(float2*)(cb_ + (r4 + 8) * 68 + col) = make_float2(d[tt][2], d[tt][3]);
        }
    }
    __syncthreads();

    if (khalf == 0) {
        const float* cb_ = comb + tile * 1088;
        #pragma unroll
        for (int tt = 0; tt < 8; tt++) {
            int col = tt * 8 + c4 * 2;
            float2 v0 = *(const float2*)(cb_ + r4 * 68 + col);
            float2 v1 = *(const float2*)(cb_ + (r4 + 8) * 68 + col);
            d[tt][0] += v0.x; d[tt][1] += v0.y;
            d[tt][2] += v1.x; d[tt][3] += v1.y;
        }

        float* gp = (kz == 0) ? g_p0 : g_p1;
        const int c_lo = cb + tile * 16 + r4;
        const int c_hi = c_lo + 8;
        float* o_lo = gp + ((size_t)n * Cc + c_lo) * HWs;
        float* o_hi = gp + ((size_t)n * Cc + c_hi) * HWs;
        #pragma unroll
        for (int tt = 0; tt < 8; tt++) {
            int col = tt * 8 + c4 * 2;
            *(float2*)(o_lo + col) = make_float2(d[tt][0], d[tt][1]);
            *(float2*)(o_hi + col) = make_float2(d[tt][2], d[tt][3]);
        }
    }
}

// =====================================================================
// Kernel 1b: combine partials + BN + SiLU -> g_f
// grid 512 x 256 threads, one float4 per thread (131072 total).
// =====================================================================
__global__ void __launch_bounds__(256)
bn_silu_kernel(const float* __restrict__ gamma,
               const float* __restrict__ beta,
               const float* __restrict__ mean,
               const float* __restrict__ var)
{
    const int i4 = blockIdx.x * 256 + threadIdx.x;      // 0..131071
    const int c  = (i4 >> 4) & (Cc - 1);                // 16 float4 per hw-row

    float4 a = ((const float4*)g_p0)[i4];
    float4 b = ((const float4*)g_p1)[i4];
    float sc = __ldg(gamma + c) * rsqrtf(__ldg(var + c) + BN_EPS);
    float bi = __ldg(beta + c) - __ldg(mean + c) * sc;

    float v0 = (a.x + b.x) * sc + bi;  v0 = v0 / (1.0f + __expf(-v0));
    float v1 = (a.y + b.y) * sc + bi;  v1 = v1 / (1.0f + __expf(-v1));
    float v2 = (a.z + b.z) * sc + bi;  v2 = v2 / (1.0f + __expf(-v2));
    float v3 = (a.w + b.w) * sc + bi;  v3 = v3 / (1.0f + __expf(-v3));

    ((float4*)g_f)[i4] = make_float4(v0, v1, v2, v3);
}

// =====================================================================
// Kernel 2: head via tf32 mma.sync  (R12/R13 winner, unchanged)
// grid (109, 16) = 1744 blocks, 160 threads = 5 warps, 8 p per block.
// =====================================================================
#define PT8   8
#define NPT   109
#define KC    32
#define NKCH  16
#define SA_F  3104               // 8 * 388
#define SF_F  (KC * 72)          // 2304
#define SMEMH_BYTES ((2 * SA_F + 2 * SF_F) * 4)   // 43264

__global__ void __launch_bounds__(160, 4)
head_mma_kernel(const float* __restrict__ weights, float* __restrict__ out)
{
    const int n    = blockIdx.y;
    const int p0   = blockIdx.x * PT8;
    const int t    = threadIdx.x;
    const int warp = t >> 5;
    const int lane = t & 31;
    const int r4   = lane >> 2;
    const int c4   = lane & 3;

    extern __shared__ __align__(16) float smem[];

    const uint32 sbase = (uint32)__cvta_generic_to_shared(smem);
    const uint32 sAbytes = SA_F * 4;
    const uint32 fbase0  = sbase + 2 * sAbytes;
    const float* gfn = g_f + (size_t)n * Cc * HWs;

    const float2* srcA[8];
    uint32 dstA[8];
    #pragma unroll
    for (int i = 0; i < 8; i++) {
        int idx = t + 160 * i;
        int pl  = idx / 160;
        int r   = idx - pl * 160;
        int p   = p0 + pl; if (p >= Pp) p = Pp - 1;
        srcA[i] = (const float2*)(weights + (size_t)(n * Pp + p) * PW) + r;
        dstA[i] = sbase + (uint32)(pl * 194 + r + r / 5) * 8;
    }

    {
        #pragma unroll
        for (int i = 0; i < 8; i++)
            asm volatile("cp.async.ca.shared.global [%0], [%1], 8;"
                         :: "r"(dstA[i]), "l"(srcA[i]) : "memory");
        #pragma unroll
        for (int i = 0; i < 4; i++) {
            int idx = t + 160 * i;
            if (idx < 512) {
                int k = idx >> 4, off = idx & 15;
                uint32 d = fbase0 + (uint32)(k * 72 + off * 4) * 4;
                asm volatile("cp.async.cg.shared.global [%0], [%1], 16;"
                             :: "r"(d), "l"(gfn + k * 64 + off * 4) : "memory");
            }
        }
        CP_COMMIT();
    }

    const int m_lo = warp * 16 + r4;
    const int m_hi = m_lo + 8;
    const int pl_lo = m_lo / 10, j_lo = m_lo - pl_lo * 10;
    const int pl_hi = m_hi / 10, j_hi = m_hi - pl_hi * 10;
    const int aoff_lo = pl_lo * 388 + j_lo + c4 * 12;
    const int aoff_hi = pl_hi * 388 + j_hi + c4 * 12;
    const int boff = c4 * 72 + r4;

    float d[8][4];
    #pragma unroll
    for (int tt = 0; tt < 8; tt++)
        #pragma unroll
        for (int k = 0; k < 4; k++) d[tt][k] = 0.0f;

    int buf = 0;
    for (int ch = 0; ch < NKCH; ch++) {
        if (ch + 1 < NKCH) {
            const uint32 abytes = (buf ^ 1) ? sAbytes : 0u;
            #pragma unroll
            for (int i = 0; i < 8; i++) {
                uint32 dd = dstA[i] + abytes;
                asm volatile("cp.async.ca.shared.global [%0], [%1], 8;"
                             :: "r"(dd), "l"(srcA[i] + (ch + 1) * 160) : "memory");
            }
            const float* fs = gfn + (ch + 1) * (KC * 64);
            const uint32 fb = fbase0 + (buf ^ 1) * (SF_F * 4);
            #pragma unroll
            for (int i = 0; i < 4; i++) {
                int idx = t + 160 * i;
                if (idx < 512) {
                    int k = idx >> 4, off = idx & 15;
                    uint32 dd = fb + (uint32)(k * 72 + off * 4) * 4;
                    asm volatile("cp.async.cg.shared.global [%0], [%1], 16;"
                                 :: "r"(dd), "l"(fs + k * 64 + off * 4) : "memory");
                }
            }
            CP_COMMIT();
            CP_WAIT1();
        } else {
            CP_WAIT0();
        }
        __syncthreads();

        const float* A = smem + buf * SA_F;
        const float* B = smem + 2 * SA_F + buf * SF_F;
        #pragma unroll
        for (int s = 0; s < 4; s++) {
            uint32 a0 = fbits(A[aoff_lo + s * 96]);
            uint32 a1 = fbits(A[aoff_hi + s * 96]);
            uint32 a2 = fbits(A[aoff_lo + s * 96 + 48]);
            uint32 a3 = fbits(A[aoff_hi + s * 96 + 48]);
            const float* Bs = B + s * 576 + boff;
            #pragma unroll
            for (int tt = 0; tt < 8; tt++) {
                uint32 b0 = fbits(Bs[tt * 8]);
                uint32 b1 = fbits(Bs[tt * 8 + 288]);
                mma_tf32(d[tt], a0, a1, a2, a3, b0, b1);
            }
        }
        __syncthreads();
        buf ^= 1;
    }

    float* L = smem;
    #pragma unroll
    for (int tt = 0; tt < 8; tt++) {
        int col = tt * 8 + c4 * 2;
        *(float2*)(L + m_lo * 68 + col) = make_float2(d[tt][0], d[tt][1]);
        *(float2*)(L + m_hi * 68 + col) = make_float2(d[tt][2], d[tt][3]);
    }
    __syncthreads();

    if (warp < 4) {
        const float inv7 = 1.0f / 7.0f;
        const int hw0 = lane * 2;
        const float x0 = (float)(hw0 & 7) * inv7;
        const float x1 = (float)((hw0 + 1) & 7) * inv7;
        const float yv = (float)(hw0 >> 3) * inv7;

        #pragma unroll
        for (int rep = 0; rep < 2; rep++) {
            const int pl = warp + rep * 4;
            const int pv = p0 + pl;
            const int p  = (pv < Pp) ? pv : (Pp - 1);

            float bias = 0.0f;
            if (lane < 10)
                bias = __ldg(weights + (size_t)(n * Pp + p) * PW + Cc * NOUT + lane);

            float l[10][2];
            #pragma unroll
            for (int j = 0; j < 10; j++) {
                float2 v = *(const float2*)(L + (pl * 10 + j) * 68 + hw0);
                float bj = __shfl_sync(0xffffffffu, bias, j);
                l[j][0] = v.x + bj;
                l[j][1] = v.y + bj;
            }

            float mx = wmax(fmaxf(l[1][0], l[1][1]));
            float e0 = __expf(l[1][0] - mx);
            float e1 = __expf(l[1][1] - mx);
            float s  = wsum(e0 + e1);
            float sx = wsum(e0 * x0 + e1 * x1);
            float sy = wsum((e0 + e1) * yv);
            float cx = sx / s;
            float cy = sy / s;

            float m2 = -INFINITY;
            #pragma unroll
            for (int j = 2; j < 10; j++)
                m2 = fmaxf(m2, fmaxf(l[j][0], l[j][1]));
            m2 = wmax(m2);

            float se = 0.0f, sx2 = 0.0f, sy2 = 0.0f, sz = 0.0f, su = 0.0f;
            #pragma unroll
            for (int j = 2; j < 10; j++) {
                float ea = __expf(l[j][0] - m2);
                float eb = __expf(l[j][1] - m2);
                float zs = (float)(j - 2) * inv7;
                se  += ea + eb;
                sx2 += ea * x0 + eb * x1;
                sy2 += (ea + eb) * yv;
                sz  += (ea + eb) * zs;
                su  += ea * l[0][0] + eb * l[0][1];
            }
            se  = wsum(se);
            sx2 = wsum(sx2);
            sy2 = wsum(sy2);
            sz  = wsum(sz);
            su  = wsum(su);

            if (lane == 0 && pv < Pp) {
                float X = sx2 / se, Y = sy2 / se, Z = sz / se, U = su / se;
                float up = fmaxf(U, 0.0f) + log1pf(__expf(-fabsf(U)));
                int gp = n * Pp + pv;
                out[gp * 2 + 0] = X;
                out[gp * 2 + 1] = Y;
                out[Nn * Pp * 2 + gp * 3 + 0] = cx;
                out[Nn * Pp * 2 + gp * 3 + 1] = cy;
                out[Nn * Pp * 2 + gp * 3 + 2] = Z;
                out[Nn * Pp * 5 + gp] = up;
            }
        }
    }
}

// =====================================================================
extern "C" void kernel_launch(void* const* d_in, const int* in_sizes, int n_in,
                              void* d_out, int out_size)
{
    const float* features = (const float*)d_in[0];
    const float* weights  = (const float*)d_in[1];
    const float* conv_w   = (const float*)d_in[2];
    const float* gamma    = (const float*)d_in[3];
    const float* beta     = (const float*)d_in[4];
    const float* mean     = (const float*)d_in[5];
    const float* var      = (const float*)d_in[6];
    float* out = (float*)d_out;

    conv_part_kernel<<<dim3(8, Nn, 2), 256>>>(features, conv_w);
    bn_silu_kernel<<<512, 256>>>(gamma, beta, mean, var);

    cudaFuncSetAttribute(head_mma_kernel,
                         cudaFuncAttributeMaxDynamicSharedMemorySize,
                         SMEMH_BYTES);
    head_mma_kernel<<<dim3(NPT, Nn), 160, SMEMH_BYTES>>>(weights, out);
}